// round 1
// baseline (speedup 1.0000x reference)
#include <cuda_runtime.h>
#include <cstdint>
#include <cstddef>

#define FULLMASK 0xFFFFFFFFu

// ---------------- problem constants (fixed shapes from reference) ------------
constexpr int B  = 32;
constexpr int H  = 768;
constexpr int KQ = 131072;

// ---------------- matmul tiling ----------------------------------------------
constexpr int KT  = 256;          // queue rows per CTA
constexpr int HC  = 64;           // h-chunk
constexpr int NCH = H / HC;       // 12
constexpr int FPITCH = 68;        // floats per smem f-row (pad: 68/2=34 ≡ 2 mod 16 -> conflict-free)
constexpr int QPITCH = 33;        // float2 per smem q h2-row (33 ≡ 1 mod 16 -> conflict-free stores)
constexpr int MMTHREADS = 128;
constexpr size_t FBYTES = (size_t)KT * FPITCH * 4;       // 69632
constexpr size_t QBYTES = (size_t)(HC / 2) * QPITCH * 8; // 8448
constexpr size_t SMEM_MM = 2 * FBYTES + 2 * QBYTES;      // 156160 B

// ---------------- scratch (device globals; no allocation allowed) -------------
__device__ unsigned int g_bufP [(size_t)B * KQ];   // pos keys, compacted per row
__device__ unsigned int g_bufN0[(size_t)B * KQ];   // neg keys ping
__device__ unsigned int g_bufN1[(size_t)B * KQ];   // neg keys pong
__device__ unsigned int g_hist [B * 256 * 32];     // per-row digit-major x chunk histograms
__device__ int g_cntP[B];
__device__ int g_cntN[B];
__device__ int g_pmm[2];                           // [0]=pos_min, [1]=neg_min
__device__ unsigned int g_posTop[B * 16];          // top-10 pos keys per row (ascending keys)

// key transform: ascending uint order == DESCENDING float order
__device__ __forceinline__ unsigned int keyOf(float f) {
    unsigned int u = __float_as_uint(f);
    return (u & 0x80000000u) ? u : (~u & 0x7FFFFFFFu);
}
__device__ __forceinline__ float valOf(unsigned int d) {
    unsigned int u = (d & 0x80000000u) ? d : (~d & 0x7FFFFFFFu);
    return __uint_as_float(u);
}

// ---------------- kernel 0: zero row counters ---------------------------------
__global__ void zero_k() {
    int t = threadIdx.x;
    if (t < B) { g_cntP[t] = 0; g_cntN[t] = 0; }
}

// ---------------- kernel 1: matmul + mask partition ---------------------------
// grid = KQ/KT CTAs, 128 threads. Register tile: 8 b x 8 k of f32x2 accumulators.
__global__ __launch_bounds__(MMTHREADS, 1)
void mm_part(const float* __restrict__ q, const float* __restrict__ fq,
             const int* __restrict__ lab_q, const int* __restrict__ clu_q,
             const int* __restrict__ lab_k, const int* __restrict__ clu_k)
{
    extern __shared__ char sm[];
    char* smF = sm;
    char* smQ = sm + 2 * FBYTES;
    const int t  = threadIdx.x;
    const int tb = t & 3;      // 4 b-groups  -> b = tb + 4*i  (conflict-free q reads)
    const int tk = t >> 2;     // 32 k-groups -> k = tk + 32*j (conflict-free f reads)
    const int k0 = blockIdx.x * KT;

    auto loadChunk = [&](int c, int bi) {
        const uint32_t fbase = (uint32_t)__cvta_generic_to_shared(smF + (size_t)bi * FBYTES);
        #pragma unroll
        for (int i = 0; i < (KT * HC / 4) / MMTHREADS; i++) {   // 32 iters
            int idx = i * MMTHREADS + t;
            int h4 = idx & 15, kk = idx >> 4;
            const float* s = fq + (size_t)(k0 + kk) * H + c * HC + h4 * 4;
            uint32_t d = fbase + (uint32_t)(kk * FPITCH + h4 * 4) * 4u;
            asm volatile("cp.async.cg.shared.global [%0], [%1], 16;" :: "r"(d), "l"(s));
        }
        const uint32_t qbase = (uint32_t)__cvta_generic_to_shared(smQ + (size_t)bi * QBYTES);
        #pragma unroll
        for (int i = 0; i < (B * HC / 2) / MMTHREADS; i++) {    // 8 iters
            int idx = i * MMTHREADS + t;
            int h2 = idx & 31, b = idx >> 5;
            const float* s = q + (size_t)b * H + c * HC + h2 * 2;
            uint32_t d = qbase + (uint32_t)(h2 * QPITCH + b) * 8u;
            asm volatile("cp.async.ca.shared.global [%0], [%1], 8;" :: "r"(d), "l"(s));
        }
        asm volatile("cp.async.commit_group;");
    };

    unsigned long long acc[8][8];
    #pragma unroll
    for (int i = 0; i < 8; i++)
        #pragma unroll
        for (int j = 0; j < 8; j++) acc[i][j] = 0ull;

    loadChunk(0, 0);
    for (int c = 0; c < NCH; c++) {
        if (c + 1 < NCH) {
            loadChunk(c + 1, (c + 1) & 1);
            asm volatile("cp.async.wait_group 1;");
        } else {
            asm volatile("cp.async.wait_group 0;");
        }
        __syncthreads();
        const unsigned long long* fb = (const unsigned long long*)(smF + (size_t)(c & 1) * FBYTES);
        const unsigned long long* qb = (const unsigned long long*)(smQ + (size_t)(c & 1) * QBYTES);
        #pragma unroll 4
        for (int h2 = 0; h2 < HC / 2; ++h2) {
            unsigned long long qa[8], fa[8];
            #pragma unroll
            for (int i = 0; i < 8; i++) qa[i] = qb[h2 * QPITCH + tb + 4 * i];
            #pragma unroll
            for (int j = 0; j < 8; j++) fa[j] = fb[(size_t)(tk + 32 * j) * (FPITCH / 2) + h2];
            #pragma unroll
            for (int i = 0; i < 8; i++)
                #pragma unroll
                for (int j = 0; j < 8; j++)
                    asm volatile("fma.rn.f32x2 %0, %1, %2, %0;"
                                 : "+l"(acc[i][j]) : "l"(qa[i]), "l"(fa[j]));
        }
        __syncthreads();
    }

    // ---- epilogue: reduce pairs, classify, compact into pos/neg buffers ----
    float sims[8][8];
    #pragma unroll
    for (int i = 0; i < 8; i++)
        #pragma unroll
        for (int j = 0; j < 8; j++) {
            float2 v = *reinterpret_cast<float2*>(&acc[i][j]);
            sims[i][j] = v.x + v.y;
        }

    int* s_clb = (int*)sm;          // 32
    int* s_lbb = s_clb + 32;        // 32
    int* s_clk = s_lbb + 32;        // 256
    int* s_lbk = s_clk + 256;       // 256
    int* s_cnt = s_lbk + 256;       // 64
    int* s_cur = s_cnt + 64;        // 64
    if (t < 32) { s_clb[t] = clu_q[t]; s_lbb[t] = lab_q[t]; }
    for (int i = t; i < KT; i += MMTHREADS) { s_clk[i] = clu_k[k0 + i]; s_lbk[i] = lab_k[k0 + i]; }
    if (t < 64) s_cnt[t] = 0;
    __syncthreads();

    #pragma unroll
    for (int i = 0; i < 8; i++) {
        int b = tb + 4 * i;
        #pragma unroll
        for (int j = 0; j < 8; j++) {
            int k = tk + 32 * j;
            int neg = (s_clk[k] == s_clb[b]) != (s_lbk[k] == s_lbb[b]);
            atomicAdd(&s_cnt[b * 2 + neg], 1);
        }
    }
    __syncthreads();
    if (t < 64) {
        int b = t >> 1; int neg = t & 1;
        int c = s_cnt[t];
        int base = 0;
        if (c) base = atomicAdd(neg ? &g_cntN[b] : &g_cntP[b], c);
        s_cur[t] = base;
    }
    __syncthreads();
    #pragma unroll
    for (int i = 0; i < 8; i++) {
        int b = tb + 4 * i;
        #pragma unroll
        for (int j = 0; j < 8; j++) {
            int k = tk + 32 * j;
            int neg = (s_clk[k] == s_clb[b]) != (s_lbk[k] == s_lbb[b]);
            int idx = atomicAdd(&s_cur[b * 2 + neg], 1);
            unsigned int key = keyOf(sims[i][j]);
            (neg ? g_bufN0 : g_bufP)[(size_t)b * KQ + idx] = key;
        }
    }
}

// ---------------- kernel 2: pos_min / neg_min ---------------------------------
__global__ void minmax_k(const int* __restrict__ topk) {
    int t = threadIdx.x;
    int cp = g_cntP[t], cn = g_cntN[t];
    #pragma unroll
    for (int off = 16; off; off >>= 1) {
        cp = min(cp, __shfl_down_sync(FULLMASK, cp, off));
        cn = min(cn, __shfl_down_sync(FULLMASK, cn, off));
    }
    if (t == 0) { g_pmm[0] = min(cp, topk[0]); g_pmm[1] = cn; }
}

// ---------------- kernel 3: top-10 of positives per row -----------------------
__global__ void pos_select() {
    int row = blockIdx.x;
    int n = g_cntP[row];
    const unsigned int* src = g_bufP + (size_t)row * KQ;
    int t = threadIdx.x;
    unsigned int best[10];
    #pragma unroll
    for (int i = 0; i < 10; i++) best[i] = 0xFFFFFFFFu;
    for (int i = t; i < n; i += 256) {
        unsigned int k = src[i];
        if (k < best[9]) {
            int j = 9;
            #pragma unroll
            for (int s = 0; s < 9; s++) {
                if (j > 0 && best[j - 1] > k) { best[j] = best[j - 1]; j--; }
            }
            best[j] = k;
        }
    }
    __shared__ unsigned int sh[256 * 10];
    #pragma unroll
    for (int i = 0; i < 10; i++) sh[t * 10 + i] = best[i];
    __syncthreads();
    for (int s = 128; s > 0; s >>= 1) {
        if (t < s) {
            unsigned int* a  = &sh[t * 10];
            unsigned int* bl = &sh[(t + s) * 10];
            unsigned int out[10]; int ia = 0, ib = 0;
            #pragma unroll
            for (int i = 0; i < 10; i++) {
                unsigned int va = (ia < 10) ? a[ia]  : 0xFFFFFFFFu;
                unsigned int vb = (ib < 10) ? bl[ib] : 0xFFFFFFFFu;
                if (va <= vb) { out[i] = va; ia++; } else { out[i] = vb; ib++; }
            }
            #pragma unroll
            for (int i = 0; i < 10; i++) a[i] = out[i];
        }
        __syncthreads();
    }
    if (t < 10) g_posTop[row * 16 + t] = sh[t];
}

// ---------------- radix sort (4x8-bit LSD), multi-kernel per pass -------------
__global__ void rs_hist(int shift, int srcSel) {
    int chunk = blockIdx.x, row = blockIdx.y;
    int n = g_cntN[row];
    int s0 = chunk * 4096;
    __shared__ int h[256];
    int t = threadIdx.x;
    h[t] = 0;
    __syncthreads();
    if (s0 < n) {
        const unsigned int* in = (srcSel ? g_bufN1 : g_bufN0) + (size_t)row * KQ;
        int lim = min(4096, n - s0);
        for (int i = t; i < lim; i += 256)
            atomicAdd(&h[(in[s0 + i] >> shift) & 255], 1);
    }
    __syncthreads();
    g_hist[row * 8192 + t * 32 + chunk] = h[t];
}

__global__ void rs_scan() {
    int row = blockIdx.x;
    unsigned int* a = g_hist + row * 8192;
    int t = threadIdx.x;
    int v[32]; int sum = 0;
    int base = t * 32;
    #pragma unroll
    for (int i = 0; i < 32; i++) { v[i] = (int)a[base + i]; sum += v[i]; }
    __shared__ int ps[256];
    ps[t] = sum;
    __syncthreads();
    for (int off = 1; off < 256; off <<= 1) {
        int x = (t >= off) ? ps[t - off] : 0;
        __syncthreads();
        ps[t] += x;
        __syncthreads();
    }
    int run = (t > 0) ? ps[t - 1] : 0;
    #pragma unroll
    for (int i = 0; i < 32; i++) { int tmp = v[i]; a[base + i] = (unsigned)run; run += tmp; }
}

__global__ void rs_scatter(int shift, int srcSel) {
    int chunk = blockIdx.x, row = blockIdx.y;
    int n = g_cntN[row];
    int s0 = chunk * 4096;
    if (s0 >= n) return;
    const unsigned int* in  = (srcSel ? g_bufN1 : g_bufN0) + (size_t)row * KQ;
    unsigned int*       out = (srcSel ? g_bufN0 : g_bufN1) + (size_t)row * KQ;
    __shared__ int sbase[256];
    __shared__ int running[256];
    __shared__ int wc[8 * 256];
    int t = threadIdx.x;
    int w = t >> 5, lane = t & 31;
    sbase[t] = (int)g_hist[row * 8192 + t * 32 + chunk];
    running[t] = 0;
    __syncthreads();
    for (int j = 0; j < 16; j++) {
        #pragma unroll
        for (int qq = 0; qq < 8; ++qq) wc[qq * 256 + t] = 0;
        __syncthreads();
        int idx = s0 + j * 256 + t;
        bool valid = idx < n;
        unsigned int key = valid ? in[idx] : 0u;
        int d = (key >> shift) & 255;
        unsigned int vm = __ballot_sync(FULLMASK, valid);
        unsigned int peers = FULLMASK;
        #pragma unroll
        for (int bb = 0; bb < 8; ++bb) {
            unsigned int vote = __ballot_sync(FULLMASK, (d >> bb) & 1);
            peers &= ((d >> bb) & 1) ? vote : ~vote;
        }
        peers &= vm;
        int rank = __popc(peers & ((1u << lane) - 1u));
        if (valid && rank == 0) atomicAdd(&wc[w * 256 + d], __popc(peers));
        __syncthreads();
        {   // thread t owns digit t: scan warp counts -> warp bases, bump running
            int off = running[t];
            #pragma unroll
            for (int ww = 0; ww < 8; ++ww) {
                int c2 = wc[ww * 256 + t];
                wc[ww * 256 + t] = off;
                off += c2;
            }
            running[t] = off;
        }
        __syncthreads();
        if (valid) out[sbase[d] + wc[w * 256 + d] + rank] = key;
        __syncthreads();
    }
}

// ---------------- writer: replicate torch view/repeat/view exactly ------------
// out[b,p][0]   = pos_top[b][p]
// out[b,p][j+1] = neg_sorted[b][ (p*nm + j) / pm ]
__global__ void write_k(float* __restrict__ out, int total) {
    int e = blockIdx.x * 256 + threadIdx.x;
    if (e >= total) return;
    unsigned int pm = (unsigned int)g_pmm[0];
    unsigned int nm = (unsigned int)g_pmm[1];
    unsigned int width = nm + 1u;
    unsigned int r = (unsigned int)e / width;
    unsigned int c = (unsigned int)e - r * width;
    unsigned int b = r / pm;
    unsigned int p = r - b * pm;
    unsigned int key;
    if (c == 0) {
        key = g_posTop[b * 16 + p];
    } else {
        unsigned int qi = (p * nm + (c - 1u)) / pm;
        key = g_bufN0[(size_t)b * KQ + qi];
    }
    out[e] = valOf(key) / 0.07f;
}

// ---------------- launcher ----------------------------------------------------
extern "C" void kernel_launch(void* const* d_in, const int* in_sizes, int n_in,
                              void* d_out, int out_size) {
    const float* q     = (const float*)d_in[0];
    const float* fq    = (const float*)d_in[1];
    const int* lab_q   = (const int*)d_in[2];
    const int* clu_q   = (const int*)d_in[3];
    const int* lab_k   = (const int*)d_in[4];
    const int* clu_k   = (const int*)d_in[5];
    const int* topk    = (const int*)d_in[6];
    float* out = (float*)d_out;

    cudaFuncSetAttribute(mm_part, cudaFuncAttributeMaxDynamicSharedMemorySize, (int)SMEM_MM);

    zero_k<<<1, 32>>>();
    mm_part<<<KQ / KT, MMTHREADS, SMEM_MM>>>(q, fq, lab_q, clu_q, lab_k, clu_k);
    minmax_k<<<1, 32>>>(topk);
    pos_select<<<B, 256>>>();
    for (int pass = 0; pass < 4; ++pass) {
        int shift = pass * 8;
        int srcSel = pass & 1;          // pass0: N0->N1, pass1: N1->N0, ... final in N0
        rs_hist<<<dim3(32, B), 256>>>(shift, srcSel);
        rs_scan<<<B, 256>>>();
        rs_scatter<<<dim3(32, B), 256>>>(shift, srcSel);
    }
    write_k<<<(out_size + 255) / 256, 256>>>(out, out_size);
}

// round 2
// speedup vs baseline: 1.1205x; 1.1205x over previous
#include <cuda_runtime.h>
#include <cstdint>
#include <cstddef>

#define FULLMASK 0xFFFFFFFFu

// ---------------- problem constants (fixed shapes from reference) ------------
constexpr int B  = 32;
constexpr int H  = 768;
constexpr int KQ = 131072;

// ---------------- matmul tiling ----------------------------------------------
constexpr int KT  = 256;          // queue rows per CTA
constexpr int HC  = 64;           // h-chunk
constexpr int NCH = H / HC;       // 12
constexpr int FPITCH = 68;        // floats per smem f-row
constexpr int QPITCH = 33;        // float2 per smem q h2-row
constexpr int MMTHREADS = 128;
constexpr size_t FBYTES = (size_t)KT * FPITCH * 4;       // 69632
constexpr size_t QBYTES = (size_t)(HC / 2) * QPITCH * 8; // 8448
constexpr size_t SMEM_MM = 2 * FBYTES + 2 * QBYTES;      // 156160 B

// ---------------- scratch (device globals; no allocation allowed) -------------
__device__ unsigned int g_bufP [(size_t)B * KQ];   // pos keys, compacted per row
__device__ unsigned int g_bufN0[(size_t)B * KQ];   // neg keys ping
__device__ unsigned int g_bufN1[(size_t)B * KQ];   // neg keys pong
__device__ unsigned int g_histA[B * 8192];         // per-row digit-major x chunk
__device__ unsigned int g_histB[B * 8192];
__device__ int g_cntP[B];
__device__ int g_cntN[B];
__device__ int g_pmm[2];                           // [0]=pos_min, [1]=neg_min
__device__ unsigned int g_posPart[B * 16 * 10];    // per-(row,chunk) top10
__device__ unsigned int g_posTop[B * 16];          // top-10 pos keys per row

// key transform: ascending uint order == DESCENDING float order
__device__ __forceinline__ unsigned int keyOf(float f) {
    unsigned int u = __float_as_uint(f);
    return (u & 0x80000000u) ? u : (~u & 0x7FFFFFFFu);
}
__device__ __forceinline__ float valOf(unsigned int d) {
    unsigned int u = (d & 0x80000000u) ? d : (~d & 0x7FFFFFFFu);
    return __uint_as_float(u);
}

// ---------------- kernel 0: zero row counters ---------------------------------
__global__ void zero_k() {
    int t = threadIdx.x;
    if (t < B) { g_cntP[t] = 0; g_cntN[t] = 0; }
}

// ---------------- kernel 1: matmul + mask partition ---------------------------
__global__ __launch_bounds__(MMTHREADS, 1)
void mm_part(const float* __restrict__ q, const float* __restrict__ fq,
             const int* __restrict__ lab_q, const int* __restrict__ clu_q,
             const int* __restrict__ lab_k, const int* __restrict__ clu_k)
{
    extern __shared__ char sm[];
    char* smF = sm;
    char* smQ = sm + 2 * FBYTES;
    const int t  = threadIdx.x;
    const int tb = t & 3;
    const int tk = t >> 2;
    const int k0 = blockIdx.x * KT;

    auto loadChunk = [&](int c, int bi) {
        const uint32_t fbase = (uint32_t)__cvta_generic_to_shared(smF + (size_t)bi * FBYTES);
        #pragma unroll
        for (int i = 0; i < (KT * HC / 4) / MMTHREADS; i++) {
            int idx = i * MMTHREADS + t;
            int h4 = idx & 15, kk = idx >> 4;
            const float* s = fq + (size_t)(k0 + kk) * H + c * HC + h4 * 4;
            uint32_t d = fbase + (uint32_t)(kk * FPITCH + h4 * 4) * 4u;
            asm volatile("cp.async.cg.shared.global [%0], [%1], 16;" :: "r"(d), "l"(s));
        }
        const uint32_t qbase = (uint32_t)__cvta_generic_to_shared(smQ + (size_t)bi * QBYTES);
        #pragma unroll
        for (int i = 0; i < (B * HC / 2) / MMTHREADS; i++) {
            int idx = i * MMTHREADS + t;
            int h2 = idx & 31, b = idx >> 5;
            const float* s = q + (size_t)b * H + c * HC + h2 * 2;
            uint32_t d = qbase + (uint32_t)(h2 * QPITCH + b) * 8u;
            asm volatile("cp.async.ca.shared.global [%0], [%1], 8;" :: "r"(d), "l"(s));
        }
        asm volatile("cp.async.commit_group;");
    };

    unsigned long long acc[8][8];
    #pragma unroll
    for (int i = 0; i < 8; i++)
        #pragma unroll
        for (int j = 0; j < 8; j++) acc[i][j] = 0ull;

    loadChunk(0, 0);
    for (int c = 0; c < NCH; c++) {
        if (c + 1 < NCH) {
            loadChunk(c + 1, (c + 1) & 1);
            asm volatile("cp.async.wait_group 1;");
        } else {
            asm volatile("cp.async.wait_group 0;");
        }
        __syncthreads();
        const unsigned long long* fb = (const unsigned long long*)(smF + (size_t)(c & 1) * FBYTES);
        const unsigned long long* qb = (const unsigned long long*)(smQ + (size_t)(c & 1) * QBYTES);
        #pragma unroll 4
        for (int h2 = 0; h2 < HC / 2; ++h2) {
            unsigned long long qa[8], fa[8];
            #pragma unroll
            for (int i = 0; i < 8; i++) qa[i] = qb[h2 * QPITCH + tb + 4 * i];
            #pragma unroll
            for (int j = 0; j < 8; j++) fa[j] = fb[(size_t)(tk + 32 * j) * (FPITCH / 2) + h2];
            #pragma unroll
            for (int i = 0; i < 8; i++)
                #pragma unroll
                for (int j = 0; j < 8; j++)
                    asm volatile("fma.rn.f32x2 %0, %1, %2, %0;"
                                 : "+l"(acc[i][j]) : "l"(qa[i]), "l"(fa[j]));
        }
        __syncthreads();
    }

    float sims[8][8];
    #pragma unroll
    for (int i = 0; i < 8; i++)
        #pragma unroll
        for (int j = 0; j < 8; j++) {
            float2 v = *reinterpret_cast<float2*>(&acc[i][j]);
            sims[i][j] = v.x + v.y;
        }

    int* s_clb = (int*)sm;
    int* s_lbb = s_clb + 32;
    int* s_clk = s_lbb + 32;
    int* s_lbk = s_clk + 256;
    int* s_cnt = s_lbk + 256;
    int* s_cur = s_cnt + 64;
    if (t < 32) { s_clb[t] = clu_q[t]; s_lbb[t] = lab_q[t]; }
    for (int i = t; i < KT; i += MMTHREADS) { s_clk[i] = clu_k[k0 + i]; s_lbk[i] = lab_k[k0 + i]; }
    if (t < 64) s_cnt[t] = 0;
    __syncthreads();

    #pragma unroll
    for (int i = 0; i < 8; i++) {
        int b = tb + 4 * i;
        #pragma unroll
        for (int j = 0; j < 8; j++) {
            int k = tk + 32 * j;
            int neg = (s_clk[k] == s_clb[b]) != (s_lbk[k] == s_lbb[b]);
            atomicAdd(&s_cnt[b * 2 + neg], 1);
        }
    }
    __syncthreads();
    if (t < 64) {
        int b = t >> 1; int neg = t & 1;
        int c = s_cnt[t];
        int base = 0;
        if (c) base = atomicAdd(neg ? &g_cntN[b] : &g_cntP[b], c);
        s_cur[t] = base;
    }
    __syncthreads();
    #pragma unroll
    for (int i = 0; i < 8; i++) {
        int b = tb + 4 * i;
        #pragma unroll
        for (int j = 0; j < 8; j++) {
            int k = tk + 32 * j;
            int neg = (s_clk[k] == s_clb[b]) != (s_lbk[k] == s_lbb[b]);
            int idx = atomicAdd(&s_cur[b * 2 + neg], 1);
            unsigned int key = keyOf(sims[i][j]);
            (neg ? g_bufN0 : g_bufP)[(size_t)b * KQ + idx] = key;
        }
    }
}

// ---------------- kernel 2: pos_min / neg_min ---------------------------------
__global__ void minmax_k(const int* __restrict__ topk) {
    int t = threadIdx.x;
    int cp = g_cntP[t], cn = g_cntN[t];
    #pragma unroll
    for (int off = 16; off; off >>= 1) {
        cp = min(cp, __shfl_down_sync(FULLMASK, cp, off));
        cn = min(cn, __shfl_down_sync(FULLMASK, cn, off));
    }
    if (t == 0) { g_pmm[0] = min(cp, topk[0]); g_pmm[1] = cn; }
}

// ---------------- top-10 of positives: partial pass (parallel, MLP=4) ---------
__device__ __forceinline__ void insert10(unsigned int (&best)[10], unsigned int k) {
    if (k < best[9]) {
        int j = 9;
        #pragma unroll
        for (int s = 0; s < 9; s++) {
            if (j > 0 && best[j - 1] > k) { best[j] = best[j - 1]; j--; }
        }
        best[j] = k;
    }
}

__global__ void pos_part() {
    int c = blockIdx.x, row = blockIdx.y;
    int n = g_cntP[row];
    int per = (n + 15) >> 4;
    int s = c * per, e = min(s + per, n);
    const unsigned int* src = g_bufP + (size_t)row * KQ;
    int t = threadIdx.x;
    unsigned int best[10];
    #pragma unroll
    for (int i = 0; i < 10; i++) best[i] = 0xFFFFFFFFu;
    for (int base = s; base < e; base += 1024) {
        unsigned int k0 = (base + 0 * 256 + t < e) ? src[base + 0 * 256 + t] : 0xFFFFFFFFu;
        unsigned int k1 = (base + 1 * 256 + t < e) ? src[base + 1 * 256 + t] : 0xFFFFFFFFu;
        unsigned int k2 = (base + 2 * 256 + t < e) ? src[base + 2 * 256 + t] : 0xFFFFFFFFu;
        unsigned int k3 = (base + 3 * 256 + t < e) ? src[base + 3 * 256 + t] : 0xFFFFFFFFu;
        insert10(best, k0); insert10(best, k1); insert10(best, k2); insert10(best, k3);
    }
    __shared__ unsigned int sh[256 * 10];
    #pragma unroll
    for (int i = 0; i < 10; i++) sh[t * 10 + i] = best[i];
    __syncthreads();
    for (int s2 = 128; s2 > 0; s2 >>= 1) {
        if (t < s2) {
            unsigned int* a  = &sh[t * 10];
            unsigned int* bl = &sh[(t + s2) * 10];
            unsigned int out[10]; int ia = 0, ib = 0;
            #pragma unroll
            for (int i = 0; i < 10; i++) {
                unsigned int va = (ia < 10) ? a[ia]  : 0xFFFFFFFFu;
                unsigned int vb = (ib < 10) ? bl[ib] : 0xFFFFFFFFu;
                if (va <= vb) { out[i] = va; ia++; } else { out[i] = vb; ib++; }
            }
            #pragma unroll
            for (int i = 0; i < 10; i++) a[i] = out[i];
        }
        __syncthreads();
    }
    if (t < 10) g_posPart[(row * 16 + c) * 10 + t] = sh[t];
}

// ---------------- top-10 of positives: merge 16 partial lists -----------------
__global__ void pos_merge() {
    int row = blockIdx.x;
    int lane = threadIdx.x;
    unsigned int v[5];
    #pragma unroll
    for (int j = 0; j < 5; j++) v[j] = g_posPart[row * 160 + lane * 5 + j];
    for (int i = 0; i < 10; i++) {
        unsigned int lmin = v[0];
        #pragma unroll
        for (int j = 1; j < 5; j++) lmin = min(lmin, v[j]);
        unsigned int wmin = lmin;
        #pragma unroll
        for (int off = 16; off; off >>= 1)
            wmin = min(wmin, __shfl_xor_sync(FULLMASK, wmin, off));
        unsigned int bal = __ballot_sync(FULLMASK, lmin == wmin);
        int leader = __ffs(bal) - 1;
        if (lane == leader) {
            bool done = false;
            #pragma unroll
            for (int j = 0; j < 5; j++) {
                if (!done && v[j] == wmin) { v[j] = 0xFFFFFFFFu; done = true; }
            }
        }
        if (lane == 0) g_posTop[row * 16 + i] = wmin;
    }
}

// ---------------- radix sort (4x8-bit LSD) ------------------------------------
// pass 0 histogram (counts only); later passes' histograms are produced by the
// previous scatter (digit histograms are permutation-invariant per pass).
__global__ void rs_hist() {
    int chunk = blockIdx.x, row = blockIdx.y;
    int n = g_cntN[row];
    int s0 = chunk * 4096;
    __shared__ int h[256];
    int t = threadIdx.x;
    h[t] = 0;
    __syncthreads();
    if (s0 < n) {
        const unsigned int* in = g_bufN0 + (size_t)row * KQ;
        int lim = min(4096, n - s0);
        for (int i = t; i < lim; i += 256)
            atomicAdd(&h[in[s0 + i] & 255], 1);
    }
    __syncthreads();
    g_histA[row * 8192 + t * 32 + chunk] = h[t];
}

// scan hist(sel) in place (counts -> flattened exclusive bases) and zero the
// other buffer so the next scatter can accumulate into it.
__global__ void rs_scan(int sel) {
    int row = blockIdx.x;
    unsigned int* a = (sel ? g_histB : g_histA) + row * 8192;
    unsigned int* z = (sel ? g_histA : g_histB) + row * 8192;
    int t = threadIdx.x;
    int v[32]; int sum = 0;
    int base = t * 32;
    #pragma unroll
    for (int i = 0; i < 32; i++) { v[i] = (int)a[base + i]; sum += v[i]; }
    __shared__ int ps[256];
    ps[t] = sum;
    __syncthreads();
    for (int off = 1; off < 256; off <<= 1) {
        int x = (t >= off) ? ps[t - off] : 0;
        __syncthreads();
        ps[t] += x;
        __syncthreads();
    }
    int run = (t > 0) ? ps[t - 1] : 0;
    #pragma unroll
    for (int i = 0; i < 32; i++) { int tmp = v[i]; a[base + i] = (unsigned)run; run += tmp; }
    #pragma unroll
    for (int i = 0; i < 32; i++) z[base + i] = 0u;
}

// scatter with register prefetch (MLP=16), smem digit staging (coalesced global
// writes in digit runs) and fused next-pass histogram accumulation.
__global__ __launch_bounds__(256)
void rs_scatter(int shift, int srcSel, int lastPass) {
    int chunk = blockIdx.x, row = blockIdx.y;
    int n = g_cntN[row];
    int s0 = chunk * 4096;
    if (s0 >= n) return;
    const unsigned int* in  = (srcSel ? g_bufN1 : g_bufN0) + (size_t)row * KQ;
    unsigned int*       out = (srcSel ? g_bufN0 : g_bufN1) + (size_t)row * KQ;
    const unsigned int* Hb  = (srcSel ? g_histB : g_histA) + row * 8192;
    unsigned int*       nh  = (srcSel ? g_histA : g_histB) + row * 8192;

    __shared__ unsigned int sKeys[4096];
    __shared__ int wc[8 * 256];
    __shared__ int gb[256];
    __shared__ int lofs[256];
    __shared__ int running[256];
    __shared__ int ps[256];

    int t = threadIdx.x;
    int w = t >> 5, lane = t & 31;

    // prefetch all 16 keys (coalesced, MLP=16)
    unsigned int myKeys[16];
    #pragma unroll
    for (int j = 0; j < 16; j++) {
        int idx = s0 + j * 256 + t;
        myKeys[j] = (idx < n) ? in[idx] : 0u;
    }

    // per-(digit,this chunk) base and count from adjacent scanned bases
    int flat = t * 32 + chunk;
    int base = (int)Hb[flat];
    int nxt = (flat + 1 < 8192) ? (int)Hb[flat + 1] : n;
    int cnt = nxt - base;
    gb[t] = base;
    ps[t] = cnt;
    running[t] = 0;
    __syncthreads();
    for (int off = 1; off < 256; off <<= 1) {
        int x = (t >= off) ? ps[t - off] : 0;
        __syncthreads();
        ps[t] += x;
        __syncthreads();
    }
    lofs[t] = ps[t] - cnt;   // exclusive
    __syncthreads();

    // stable ranking rounds -> stage into smem ordered by digit
    for (int j = 0; j < 16; j++) {
        #pragma unroll
        for (int qq = 0; qq < 8; ++qq) wc[qq * 256 + t] = 0;
        __syncthreads();
        int idx = s0 + j * 256 + t;
        bool valid = idx < n;
        unsigned int key = myKeys[j];
        int d = (key >> shift) & 255;
        unsigned int vm = __ballot_sync(FULLMASK, valid);
        unsigned int peers = FULLMASK;
        #pragma unroll
        for (int bb = 0; bb < 8; ++bb) {
            unsigned int vote = __ballot_sync(FULLMASK, (d >> bb) & 1);
            peers &= ((d >> bb) & 1) ? vote : ~vote;
        }
        peers &= vm;
        int rank = __popc(peers & ((1u << lane) - 1u));
        if (valid && rank == 0) atomicAdd(&wc[w * 256 + d], __popc(peers));
        __syncthreads();
        {
            int off = running[t];
            #pragma unroll
            for (int ww = 0; ww < 8; ++ww) {
                int c2 = wc[ww * 256 + t];
                wc[ww * 256 + t] = off;
                off += c2;
            }
            running[t] = off;
        }
        __syncthreads();
        if (valid) sKeys[lofs[d] + wc[w * 256 + d] + rank] = key;
        __syncthreads();
    }

    // coalesced copy-out in digit runs + fused next-pass histogram
    int lim = min(4096, n - s0);
    for (int pos = t; pos < lim; pos += 256) {
        unsigned int key = sKeys[pos];
        int d = (key >> shift) & 255;
        int dst = gb[d] + (pos - lofs[d]);
        out[dst] = key;
        if (!lastPass) {
            int nd = (key >> (shift + 8)) & 255;
            atomicAdd(&nh[nd * 32 + (dst >> 12)], 1u);
        }
    }
}

// ---------------- writer: replicate torch view/repeat/view exactly ------------
// out[b,p][0]   = pos_top[b][p]
// out[b,p][j+1] = neg_sorted[b][ (p*nm + j) / pm ]
// grid (4 quarters, 320 rows); incremental qi update (one div per thread)
__global__ void write_k(float* __restrict__ out) {
    int r = blockIdx.y;
    unsigned int pm = (unsigned int)g_pmm[0];
    unsigned int nm = (unsigned int)g_pmm[1];
    if ((unsigned)r >= 32u * pm) return;
    unsigned int width = nm + 1u;
    unsigned int b = (unsigned)r / pm;
    unsigned int p = (unsigned)r - b * pm;
    const float invT = 1.0f / 0.07f;
    size_t rowBase = (size_t)r * width;
    const unsigned int* negRow = g_bufN0 + (size_t)b * KQ;

    unsigned int qlen = (width + 3u) >> 2;
    unsigned int c = blockIdx.x * qlen + threadIdx.x;
    unsigned int cend = min((blockIdx.x + 1u) * qlen, width);
    if (c >= cend) return;
    if (c == 0u) {
        out[rowBase] = valOf(g_posTop[b * 16 + p]) * invT;
        c += 256u;
        if (c >= cend) return;
    }
    unsigned int num = p * nm + (c - 1u);
    unsigned int qi = num / pm;
    unsigned int rem = num - qi * pm;
    unsigned int d256 = 256u / pm;
    unsigned int r256 = 256u - d256 * pm;
    while (c < cend) {
        out[rowBase + c] = valOf(negRow[qi]) * invT;
        c += 256u;
        qi += d256;
        rem += r256;
        if (rem >= pm) { rem -= pm; qi += 1u; }
    }
}

// ---------------- launcher ----------------------------------------------------
extern "C" void kernel_launch(void* const* d_in, const int* in_sizes, int n_in,
                              void* d_out, int out_size) {
    const float* q     = (const float*)d_in[0];
    const float* fq    = (const float*)d_in[1];
    const int* lab_q   = (const int*)d_in[2];
    const int* clu_q   = (const int*)d_in[3];
    const int* lab_k   = (const int*)d_in[4];
    const int* clu_k   = (const int*)d_in[5];
    const int* topk    = (const int*)d_in[6];
    float* out = (float*)d_out;

    cudaFuncSetAttribute(mm_part, cudaFuncAttributeMaxDynamicSharedMemorySize, (int)SMEM_MM);

    zero_k<<<1, 32>>>();
    mm_part<<<KQ / KT, MMTHREADS, SMEM_MM>>>(q, fq, lab_q, clu_q, lab_k, clu_k);
    minmax_k<<<1, 32>>>(topk);
    pos_part<<<dim3(16, B), 256>>>();
    pos_merge<<<B, 32>>>();
    rs_hist<<<dim3(32, B), 256>>>();
    for (int pass = 0; pass < 4; ++pass) {
        rs_scan<<<B, 256>>>(pass & 1);
        rs_scatter<<<dim3(32, B), 256>>>(pass * 8, pass & 1, pass == 3);
    }
    write_k<<<dim3(4, 320), 256>>>(out);
}

// round 3
// speedup vs baseline: 1.3366x; 1.1928x over previous
#include <cuda_runtime.h>
#include <cstdint>
#include <cstddef>

#define FULLMASK 0xFFFFFFFFu

// ---------------- problem constants ------------------------------------------
constexpr int B  = 32;
constexpr int H  = 768;
constexpr int KQ = 131072;

// ---------------- matmul tiling ----------------------------------------------
constexpr int KT  = 256;          // queue rows per CTA
constexpr int HC  = 32;           // h-chunk (small -> 2 CTAs/SM)
constexpr int NCH = H / HC;       // 24
constexpr int FWPR = 36;          // words per f-row (32 + 4 pad; /2=18 ≡ 2 mod 16)
constexpr int MMTHREADS = 128;
constexpr size_t FBYTES = (size_t)KT * FWPR * 4;   // 36864
constexpr size_t QBYTES = (size_t)B * FWPR * 4;    // 4608
constexpr size_t SMEM_MM = 2 * FBYTES + 2 * QBYTES; // 82944 B  (x2 CTAs = 162KB)

// ---------------- scratch ----------------------------------------------------
__device__ unsigned int g_bufP [(size_t)B * KQ];
__device__ unsigned int g_bufN0[(size_t)B * KQ];
__device__ unsigned int g_bufN1[(size_t)B * KQ];
__device__ unsigned int g_histA[B * 8192];
__device__ int g_cntP[B];
__device__ int g_cntN[B];
__device__ int g_pmm[2];
__device__ unsigned int g_posPart[B * 16 * 10];
__device__ unsigned int g_posTop[B * 16];

__device__ __forceinline__ unsigned int keyOf(float f) {
    unsigned int u = __float_as_uint(f);
    return (u & 0x80000000u) ? u : (~u & 0x7FFFFFFFu);
}
__device__ __forceinline__ float valOf(unsigned int d) {
    unsigned int u = (d & 0x80000000u) ? d : (~d & 0x7FFFFFFFu);
    return __uint_as_float(u);
}

// ---------------- kernel 0 ----------------------------------------------------
__global__ void zero_k() {
    int t = threadIdx.x;
    if (t < B) { g_cntP[t] = 0; g_cntN[t] = 0; }
}

// ---------------- kernel 1: matmul + mask partition ---------------------------
__global__ __launch_bounds__(MMTHREADS, 2)
void mm_part(const float* __restrict__ q, const float* __restrict__ fq,
             const int* __restrict__ lab_q, const int* __restrict__ clu_q,
             const int* __restrict__ lab_k, const int* __restrict__ clu_k)
{
    extern __shared__ char sm[];
    char* smF = sm;                       // 2 x FBYTES
    char* smQ = sm + 2 * FBYTES;          // 2 x QBYTES
    const int t  = threadIdx.x;
    const int tb = t & 3;                 // b = tb + 4*i
    const int tk = t >> 2;                // k = tk + 32*j
    const int k0 = blockIdx.x * KT;

    auto loadChunk = [&](int c, int bi) {
        const uint32_t fbase = (uint32_t)__cvta_generic_to_shared(smF + (size_t)bi * FBYTES);
        #pragma unroll
        for (int i = 0; i < (KT * HC / 4) / MMTHREADS; i++) {   // 16 iters
            int idx = i * MMTHREADS + t;
            int h4 = idx & 7, kk = idx >> 3;
            const float* s = fq + (size_t)(k0 + kk) * H + c * HC + h4 * 4;
            uint32_t d = fbase + (uint32_t)(kk * FWPR + h4 * 4) * 4u;
            asm volatile("cp.async.cg.shared.global [%0], [%1], 16;" :: "r"(d), "l"(s));
        }
        const uint32_t qbase = (uint32_t)__cvta_generic_to_shared(smQ + (size_t)bi * QBYTES);
        #pragma unroll
        for (int i = 0; i < (B * HC / 4) / MMTHREADS; i++) {    // 2 iters
            int idx = i * MMTHREADS + t;
            int h4 = idx & 7, b = idx >> 3;
            const float* s = q + (size_t)b * H + c * HC + h4 * 4;
            uint32_t d = qbase + (uint32_t)(b * FWPR + h4 * 4) * 4u;
            asm volatile("cp.async.ca.shared.global [%0], [%1], 16;" :: "r"(d), "l"(s));
        }
        asm volatile("cp.async.commit_group;");
    };

    unsigned long long acc[8][8];
    #pragma unroll
    for (int i = 0; i < 8; i++)
        #pragma unroll
        for (int j = 0; j < 8; j++) acc[i][j] = 0ull;

    loadChunk(0, 0);
    for (int c = 0; c < NCH; c++) {
        if (c + 1 < NCH) {
            loadChunk(c + 1, (c + 1) & 1);
            asm volatile("cp.async.wait_group 1;");
        } else {
            asm volatile("cp.async.wait_group 0;");
        }
        __syncthreads();
        const ulonglong2* fb = (const ulonglong2*)(smF + (size_t)(c & 1) * FBYTES);
        const ulonglong2* qb = (const ulonglong2*)(smQ + (size_t)(c & 1) * QBYTES);
        #pragma unroll
        for (int h4 = 0; h4 < HC / 4; ++h4) {                  // 8 iters, 2 h2 each
            ulonglong2 qa[8], fa[8];
            #pragma unroll
            for (int i = 0; i < 8; i++) qa[i] = qb[(tb + 4 * i) * (FWPR / 4) + h4];
            #pragma unroll
            for (int j = 0; j < 8; j++) fa[j] = fb[(size_t)(tk + 32 * j) * (FWPR / 4) + h4];
            #pragma unroll
            for (int i = 0; i < 8; i++)
                #pragma unroll
                for (int j = 0; j < 8; j++) {
                    asm volatile("fma.rn.f32x2 %0, %1, %2, %0;"
                                 : "+l"(acc[i][j]) : "l"(qa[i].x), "l"(fa[j].x));
                    asm volatile("fma.rn.f32x2 %0, %1, %2, %0;"
                                 : "+l"(acc[i][j]) : "l"(qa[i].y), "l"(fa[j].y));
                }
        }
        __syncthreads();
    }

    // ---- reduce pairs -> sims -----------------------------------------------
    float sims[8][8];
    #pragma unroll
    for (int i = 0; i < 8; i++)
        #pragma unroll
        for (int j = 0; j < 8; j++) {
            float2 v = *reinterpret_cast<float2*>(&acc[i][j]);
            sims[i][j] = v.x + v.y;
        }

    // ---- classification: 64-bit neg mask ------------------------------------
    int myClb[8], myLbb[8], myClk[8], myLbk[8];
    #pragma unroll
    for (int i = 0; i < 8; i++) {
        int b = tb + 4 * i;
        myClb[i] = clu_q[b]; myLbb[i] = lab_q[b];
    }
    #pragma unroll
    for (int j = 0; j < 8; j++) {
        int k = k0 + tk + 32 * j;
        myClk[j] = clu_k[k]; myLbk[j] = lab_k[k];
    }
    unsigned long long negmask = 0ull;
    #pragma unroll
    for (int i = 0; i < 8; i++)
        #pragma unroll
        for (int j = 0; j < 8; j++) {
            int neg = (myClk[j] == myClb[i]) != (myLbk[j] == myLbb[i]);
            negmask |= ((unsigned long long)neg) << (i * 8 + j);
        }

    // ---- staged, coalesced compaction ---------------------------------------
    // smem reuse (compute done; loop-final __syncthreads() protects reads)
    unsigned int* stage = (unsigned int*)sm;            // 8192 keys = 32KB
    int* s_cnt  = (int*)(sm + 32768);                   // 64
    int* s_lofs = s_cnt + 64;                           // 64
    int* s_cur  = s_lofs + 64;                          // 64
    int* s_base = s_cur + 64;                           // 64
    if (t < 64) s_cnt[t] = 0;
    __syncthreads();
    #pragma unroll
    for (int i = 0; i < 8; i++)
        #pragma unroll
        for (int j = 0; j < 8; j++) {
            int seg = (tb + 4 * i) * 2 + (int)((negmask >> (i * 8 + j)) & 1ull);
            atomicAdd(&s_cnt[seg], 1);
        }
    __syncthreads();
    if (t == 0) {
        int run = 0;
        for (int s = 0; s < 64; s++) { s_lofs[s] = run; run += s_cnt[s]; }
    }
    __syncthreads();
    if (t < 64) {
        s_cur[t] = s_lofs[t];
        int b = t >> 1, neg = t & 1;
        int c = s_cnt[t];
        s_base[t] = c ? atomicAdd(neg ? &g_cntN[b] : &g_cntP[b], c) : 0;
    }
    __syncthreads();
    #pragma unroll
    for (int i = 0; i < 8; i++)
        #pragma unroll
        for (int j = 0; j < 8; j++) {
            int seg = (tb + 4 * i) * 2 + (int)((negmask >> (i * 8 + j)) & 1ull);
            int idx = atomicAdd(&s_cur[seg], 1);
            stage[idx] = keyOf(sims[i][j]);
        }
    __syncthreads();
    // coalesced copy-out per segment
    for (int s = 0; s < 64; s++) {
        int cnt = s_cnt[s];
        int b = s >> 1, neg = s & 1;
        unsigned int* dstBuf = (neg ? g_bufN0 : g_bufP) + (size_t)b * KQ + s_base[s];
        const unsigned int* srcP = stage + s_lofs[s];
        for (int i = t; i < cnt; i += MMTHREADS) dstBuf[i] = srcP[i];
    }
}

// ---------------- kernel 2: pos_min / neg_min ---------------------------------
__global__ void minmax_k(const int* __restrict__ topk) {
    int t = threadIdx.x;
    int cp = g_cntP[t], cn = g_cntN[t];
    #pragma unroll
    for (int off = 16; off; off >>= 1) {
        cp = min(cp, __shfl_down_sync(FULLMASK, cp, off));
        cn = min(cn, __shfl_down_sync(FULLMASK, cn, off));
    }
    if (t == 0) { g_pmm[0] = min(cp, topk[0]); g_pmm[1] = cn; }
}

// ---------------- top-10 of positives -----------------------------------------
__device__ __forceinline__ void insert10(unsigned int (&best)[10], unsigned int k) {
    if (k < best[9]) {
        int j = 9;
        #pragma unroll
        for (int s = 0; s < 9; s++) {
            if (j > 0 && best[j - 1] > k) { best[j] = best[j - 1]; j--; }
        }
        best[j] = k;
    }
}

__global__ void pos_part() {
    int c = blockIdx.x, row = blockIdx.y;
    int n = g_cntP[row];
    int per = (n + 15) >> 4;
    int s = c * per, e = min(s + per, n);
    const unsigned int* src = g_bufP + (size_t)row * KQ;
    int t = threadIdx.x;
    unsigned int best[10];
    #pragma unroll
    for (int i = 0; i < 10; i++) best[i] = 0xFFFFFFFFu;
    for (int base = s; base < e; base += 1024) {
        unsigned int k0 = (base + 0 * 256 + t < e) ? src[base + 0 * 256 + t] : 0xFFFFFFFFu;
        unsigned int k1 = (base + 1 * 256 + t < e) ? src[base + 1 * 256 + t] : 0xFFFFFFFFu;
        unsigned int k2 = (base + 2 * 256 + t < e) ? src[base + 2 * 256 + t] : 0xFFFFFFFFu;
        unsigned int k3 = (base + 3 * 256 + t < e) ? src[base + 3 * 256 + t] : 0xFFFFFFFFu;
        insert10(best, k0); insert10(best, k1); insert10(best, k2); insert10(best, k3);
    }
    __shared__ unsigned int sh[256 * 10];
    #pragma unroll
    for (int i = 0; i < 10; i++) sh[t * 10 + i] = best[i];
    __syncthreads();
    for (int s2 = 128; s2 > 0; s2 >>= 1) {
        if (t < s2) {
            unsigned int* a  = &sh[t * 10];
            unsigned int* bl = &sh[(t + s2) * 10];
            unsigned int out[10]; int ia = 0, ib = 0;
            #pragma unroll
            for (int i = 0; i < 10; i++) {
                unsigned int va = (ia < 10) ? a[ia]  : 0xFFFFFFFFu;
                unsigned int vb = (ib < 10) ? bl[ib] : 0xFFFFFFFFu;
                if (va <= vb) { out[i] = va; ia++; } else { out[i] = vb; ib++; }
            }
            #pragma unroll
            for (int i = 0; i < 10; i++) a[i] = out[i];
        }
        __syncthreads();
    }
    if (t < 10) g_posPart[(row * 16 + c) * 10 + t] = sh[t];
}

__global__ void pos_merge() {
    int row = blockIdx.x;
    int lane = threadIdx.x;
    unsigned int v[5];
    #pragma unroll
    for (int j = 0; j < 5; j++) v[j] = g_posPart[row * 160 + lane * 5 + j];
    for (int i = 0; i < 10; i++) {
        unsigned int lmin = v[0];
        #pragma unroll
        for (int j = 1; j < 5; j++) lmin = min(lmin, v[j]);
        unsigned int wmin = lmin;
        #pragma unroll
        for (int off = 16; off; off >>= 1)
            wmin = min(wmin, __shfl_xor_sync(FULLMASK, wmin, off));
        unsigned int bal = __ballot_sync(FULLMASK, lmin == wmin);
        int leader = __ffs(bal) - 1;
        if (lane == leader) {
            bool done = false;
            #pragma unroll
            for (int j = 0; j < 5; j++) {
                if (!done && v[j] == wmin) { v[j] = 0xFFFFFFFFu; done = true; }
            }
        }
        if (lane == 0) g_posTop[row * 16 + i] = wmin;
    }
}

// ---------------- radix sort (4x8-bit LSD) ------------------------------------
__global__ void rs_hist(int shift, int srcSel) {
    int chunk = blockIdx.x, row = blockIdx.y;
    int n = g_cntN[row];
    int s0 = chunk * 4096;
    __shared__ int h[256];
    int t = threadIdx.x;
    h[t] = 0;
    __syncthreads();
    if (s0 < n) {
        const unsigned int* in = (srcSel ? g_bufN1 : g_bufN0) + (size_t)row * KQ;
        int lim = min(4096, n - s0);
        for (int i = t; i < lim; i += 256)
            atomicAdd(&h[(in[s0 + i] >> shift) & 255], 1);
    }
    __syncthreads();
    g_histA[row * 8192 + t * 32 + chunk] = h[t];
}

__global__ void rs_scan() {
    int row = blockIdx.x;
    unsigned int* a = g_histA + row * 8192;
    int t = threadIdx.x;
    int v[32]; int sum = 0;
    int base = t * 32;
    #pragma unroll
    for (int i = 0; i < 32; i++) { v[i] = (int)a[base + i]; sum += v[i]; }
    __shared__ int ps[256];
    ps[t] = sum;
    __syncthreads();
    for (int off = 1; off < 256; off <<= 1) {
        int x = (t >= off) ? ps[t - off] : 0;
        __syncthreads();
        ps[t] += x;
        __syncthreads();
    }
    int run = (t > 0) ? ps[t - 1] : 0;
    #pragma unroll
    for (int i = 0; i < 32; i++) { int tmp = v[i]; a[base + i] = (unsigned)run; run += tmp; }
}

__global__ __launch_bounds__(256)
void rs_scatter(int shift, int srcSel) {
    int chunk = blockIdx.x, row = blockIdx.y;
    int n = g_cntN[row];
    int s0 = chunk * 4096;
    if (s0 >= n) return;
    const unsigned int* in  = (srcSel ? g_bufN1 : g_bufN0) + (size_t)row * KQ;
    unsigned int*       out = (srcSel ? g_bufN0 : g_bufN1) + (size_t)row * KQ;
    const unsigned int* Hb  = g_histA + row * 8192;

    __shared__ unsigned int sKeys[4096];
    __shared__ int wc[8 * 256];
    __shared__ int gb[256];
    __shared__ int lofs[256];
    __shared__ int running[256];
    __shared__ int ps[256];

    int t = threadIdx.x;
    int w = t >> 5, lane = t & 31;

    unsigned int myKeys[16];
    #pragma unroll
    for (int j = 0; j < 16; j++) {
        int idx = s0 + j * 256 + t;
        myKeys[j] = (idx < n) ? in[idx] : 0u;
    }

    int flat = t * 32 + chunk;
    int base = (int)Hb[flat];
    int nxt = (flat + 1 < 8192) ? (int)Hb[flat + 1] : n;
    int cnt = nxt - base;
    gb[t] = base;
    ps[t] = cnt;
    running[t] = 0;
    __syncthreads();
    for (int off = 1; off < 256; off <<= 1) {
        int x = (t >= off) ? ps[t - off] : 0;
        __syncthreads();
        ps[t] += x;
        __syncthreads();
    }
    lofs[t] = ps[t] - cnt;
    __syncthreads();

    for (int j = 0; j < 16; j++) {
        #pragma unroll
        for (int qq = 0; qq < 8; ++qq) wc[qq * 256 + t] = 0;
        __syncthreads();
        int idx = s0 + j * 256 + t;
        bool valid = idx < n;
        unsigned int key = myKeys[j];
        int d = (key >> shift) & 255;
        unsigned int vm = __ballot_sync(FULLMASK, valid);
        unsigned int peers = FULLMASK;
        #pragma unroll
        for (int bb = 0; bb < 8; ++bb) {
            unsigned int vote = __ballot_sync(FULLMASK, (d >> bb) & 1);
            peers &= ((d >> bb) & 1) ? vote : ~vote;
        }
        peers &= vm;
        int rank = __popc(peers & ((1u << lane) - 1u));
        if (valid && rank == 0) atomicAdd(&wc[w * 256 + d], __popc(peers));
        __syncthreads();
        {
            int off = running[t];
            #pragma unroll
            for (int ww = 0; ww < 8; ++ww) {
                int c2 = wc[ww * 256 + t];
                wc[ww * 256 + t] = off;
                off += c2;
            }
            running[t] = off;
        }
        __syncthreads();
        if (valid) sKeys[lofs[d] + wc[w * 256 + d] + rank] = key;
        __syncthreads();
    }

    int lim = min(4096, n - s0);
    for (int pos = t; pos < lim; pos += 256) {
        unsigned int key = sKeys[pos];
        int d = (key >> shift) & 255;
        out[gb[d] + (pos - lofs[d])] = key;
    }
}

// ---------------- writer ------------------------------------------------------
__global__ void write_k(float* __restrict__ out) {
    int r = blockIdx.y;
    unsigned int pm = (unsigned int)g_pmm[0];
    unsigned int nm = (unsigned int)g_pmm[1];
    if ((unsigned)r >= 32u * pm) return;
    unsigned int width = nm + 1u;
    unsigned int b = (unsigned)r / pm;
    unsigned int p = (unsigned)r - b * pm;
    const float invT = 1.0f / 0.07f;
    size_t rowBase = (size_t)r * width;
    const unsigned int* negRow = g_bufN0 + (size_t)b * KQ;

    unsigned int qlen = (width + 3u) >> 2;
    unsigned int c = blockIdx.x * qlen + threadIdx.x;
    unsigned int cend = min((blockIdx.x + 1u) * qlen, width);
    if (c >= cend) return;
    if (c == 0u) {
        out[rowBase] = valOf(g_posTop[b * 16 + p]) * invT;
        c += 256u;
        if (c >= cend) return;
    }
    unsigned int num = p * nm + (c - 1u);
    unsigned int qi = num / pm;
    unsigned int rem = num - qi * pm;
    unsigned int d256 = 256u / pm;
    unsigned int r256 = 256u - d256 * pm;
    while (c < cend) {
        out[rowBase + c] = valOf(negRow[qi]) * invT;
        c += 256u;
        qi += d256;
        rem += r256;
        if (rem >= pm) { rem -= pm; qi += 1u; }
    }
}

// ---------------- launcher ----------------------------------------------------
extern "C" void kernel_launch(void* const* d_in, const int* in_sizes, int n_in,
                              void* d_out, int out_size) {
    const float* q     = (const float*)d_in[0];
    const float* fq    = (const float*)d_in[1];
    const int* lab_q   = (const int*)d_in[2];
    const int* clu_q   = (const int*)d_in[3];
    const int* lab_k   = (const int*)d_in[4];
    const int* clu_k   = (const int*)d_in[5];
    const int* topk    = (const int*)d_in[6];
    float* out = (float*)d_out;

    cudaFuncSetAttribute(mm_part, cudaFuncAttributeMaxDynamicSharedMemorySize, (int)SMEM_MM);

    zero_k<<<1, 32>>>();
    mm_part<<<KQ / KT, MMTHREADS, SMEM_MM>>>(q, fq, lab_q, clu_q, lab_k, clu_k);
    minmax_k<<<1, 32>>>(topk);
    pos_part<<<dim3(16, B), 256>>>();
    pos_merge<<<B, 32>>>();
    for (int pass = 0; pass < 4; ++pass) {
        rs_hist<<<dim3(32, B), 256>>>(pass * 8, pass & 1);
        rs_scan<<<B, 256>>>();
        rs_scatter<<<dim3(32, B), 256>>>(pass * 8, pass & 1);
    }
    write_k<<<dim3(4, 320), 256>>>(out);
}

// round 4
// speedup vs baseline: 1.5928x; 1.1917x over previous
#include <cuda_runtime.h>
#include <cstdint>
#include <cstddef>

#define FULLMASK 0xFFFFFFFFu

// ---------------- problem constants ------------------------------------------
constexpr int B  = 32;
constexpr int H  = 768;
constexpr int KQ = 131072;

// ---------------- matmul tiling ----------------------------------------------
constexpr int KT  = 256;
constexpr int HC  = 32;
constexpr int NCH = H / HC;       // 24
constexpr int FWPR = 36;
constexpr int MMTHREADS = 128;
constexpr size_t FBYTES = (size_t)KT * FWPR * 4;
constexpr size_t QBYTES = (size_t)B * FWPR * 4;
constexpr size_t SMEM_MM = 2 * FBYTES + 2 * QBYTES;   // 82944 B

// ---------------- scratch ----------------------------------------------------
__device__ unsigned int g_bufP [(size_t)B * KQ];
__device__ unsigned int g_bufN0[(size_t)B * KQ];
__device__ unsigned int g_bufN1[(size_t)B * KQ];
__device__ unsigned int g_histA[B * 8192];
__device__ int g_cntP[B];
__device__ int g_cntN[B];
__device__ int g_pmm[2];
__device__ unsigned int g_posPart[B * 16 * 10];
__device__ unsigned int g_posTop[B * 16];

__device__ __forceinline__ unsigned int keyOf(float f) {
    unsigned int u = __float_as_uint(f);
    return (u & 0x80000000u) ? u : (~u & 0x7FFFFFFFu);
}
__device__ __forceinline__ float valOf(unsigned int d) {
    unsigned int u = (d & 0x80000000u) ? d : (~d & 0x7FFFFFFFu);
    return __uint_as_float(u);
}

// ---------------- kernel 0 ----------------------------------------------------
__global__ void zero_k() {
    int t = threadIdx.x;
    if (t < B) { g_cntP[t] = 0; g_cntN[t] = 0; }
}

// ---------------- kernel 1: matmul + mask partition ---------------------------
__global__ __launch_bounds__(MMTHREADS, 2)
void mm_part(const float* __restrict__ q, const float* __restrict__ fq,
             const int* __restrict__ lab_q, const int* __restrict__ clu_q,
             const int* __restrict__ lab_k, const int* __restrict__ clu_k)
{
    extern __shared__ char sm[];
    char* smF = sm;
    char* smQ = sm + 2 * FBYTES;
    const int t  = threadIdx.x;
    const int tb = t & 3;
    const int tk = t >> 2;
    const int k0 = blockIdx.x * KT;

    auto loadChunk = [&](int c, int bi) {
        const uint32_t fbase = (uint32_t)__cvta_generic_to_shared(smF + (size_t)bi * FBYTES);
        #pragma unroll
        for (int i = 0; i < (KT * HC / 4) / MMTHREADS; i++) {
            int idx = i * MMTHREADS + t;
            int h4 = idx & 7, kk = idx >> 3;
            const float* s = fq + (size_t)(k0 + kk) * H + c * HC + h4 * 4;
            uint32_t d = fbase + (uint32_t)(kk * FWPR + h4 * 4) * 4u;
            asm volatile("cp.async.cg.shared.global [%0], [%1], 16;" :: "r"(d), "l"(s));
        }
        const uint32_t qbase = (uint32_t)__cvta_generic_to_shared(smQ + (size_t)bi * QBYTES);
        #pragma unroll
        for (int i = 0; i < (B * HC / 4) / MMTHREADS; i++) {
            int idx = i * MMTHREADS + t;
            int h4 = idx & 7, b = idx >> 3;
            const float* s = q + (size_t)b * H + c * HC + h4 * 4;
            uint32_t d = qbase + (uint32_t)(b * FWPR + h4 * 4) * 4u;
            asm volatile("cp.async.ca.shared.global [%0], [%1], 16;" :: "r"(d), "l"(s));
        }
        asm volatile("cp.async.commit_group;");
    };

    unsigned long long acc[8][8];
    #pragma unroll
    for (int i = 0; i < 8; i++)
        #pragma unroll
        for (int j = 0; j < 8; j++) acc[i][j] = 0ull;

    loadChunk(0, 0);
    for (int c = 0; c < NCH; c++) {
        if (c + 1 < NCH) {
            loadChunk(c + 1, (c + 1) & 1);
            asm volatile("cp.async.wait_group 1;");
        } else {
            asm volatile("cp.async.wait_group 0;");
        }
        __syncthreads();
        const ulonglong2* fb = (const ulonglong2*)(smF + (size_t)(c & 1) * FBYTES);
        const ulonglong2* qb = (const ulonglong2*)(smQ + (size_t)(c & 1) * QBYTES);
        #pragma unroll
        for (int h4 = 0; h4 < HC / 4; ++h4) {
            ulonglong2 qa[8], fa[8];
            #pragma unroll
            for (int i = 0; i < 8; i++) qa[i] = qb[(tb + 4 * i) * (FWPR / 4) + h4];
            #pragma unroll
            for (int j = 0; j < 8; j++) fa[j] = fb[(size_t)(tk + 32 * j) * (FWPR / 4) + h4];
            #pragma unroll
            for (int i = 0; i < 8; i++)
                #pragma unroll
                for (int j = 0; j < 8; j++) {
                    asm volatile("fma.rn.f32x2 %0, %1, %2, %0;"
                                 : "+l"(acc[i][j]) : "l"(qa[i].x), "l"(fa[j].x));
                    asm volatile("fma.rn.f32x2 %0, %1, %2, %0;"
                                 : "+l"(acc[i][j]) : "l"(qa[i].y), "l"(fa[j].y));
                }
        }
        __syncthreads();
    }

    float sims[8][8];
    #pragma unroll
    for (int i = 0; i < 8; i++)
        #pragma unroll
        for (int j = 0; j < 8; j++) {
            float2 v = *reinterpret_cast<float2*>(&acc[i][j]);
            sims[i][j] = v.x + v.y;
        }

    int myClb[8], myLbb[8], myClk[8], myLbk[8];
    #pragma unroll
    for (int i = 0; i < 8; i++) {
        int b = tb + 4 * i;
        myClb[i] = clu_q[b]; myLbb[i] = lab_q[b];
    }
    #pragma unroll
    for (int j = 0; j < 8; j++) {
        int k = k0 + tk + 32 * j;
        myClk[j] = clu_k[k]; myLbk[j] = lab_k[k];
    }
    unsigned long long negmask = 0ull;
    #pragma unroll
    for (int i = 0; i < 8; i++)
        #pragma unroll
        for (int j = 0; j < 8; j++) {
            int neg = (myClk[j] == myClb[i]) != (myLbk[j] == myLbb[i]);
            negmask |= ((unsigned long long)neg) << (i * 8 + j);
        }

    unsigned int* stage = (unsigned int*)sm;
    int* s_cnt  = (int*)(sm + 32768);
    int* s_lofs = s_cnt + 64;
    int* s_cur  = s_lofs + 64;
    int* s_base = s_cur + 64;
    if (t < 64) s_cnt[t] = 0;
    __syncthreads();
    #pragma unroll
    for (int i = 0; i < 8; i++)
        #pragma unroll
        for (int j = 0; j < 8; j++) {
            int seg = (tb + 4 * i) * 2 + (int)((negmask >> (i * 8 + j)) & 1ull);
            atomicAdd(&s_cnt[seg], 1);
        }
    __syncthreads();
    if (t == 0) {
        int run = 0;
        for (int s = 0; s < 64; s++) { s_lofs[s] = run; run += s_cnt[s]; }
    }
    __syncthreads();
    if (t < 64) {
        s_cur[t] = s_lofs[t];
        int b = t >> 1, neg = t & 1;
        int c = s_cnt[t];
        s_base[t] = c ? atomicAdd(neg ? &g_cntN[b] : &g_cntP[b], c) : 0;
    }
    __syncthreads();
    #pragma unroll
    for (int i = 0; i < 8; i++)
        #pragma unroll
        for (int j = 0; j < 8; j++) {
            int seg = (tb + 4 * i) * 2 + (int)((negmask >> (i * 8 + j)) & 1ull);
            int idx = atomicAdd(&s_cur[seg], 1);
            stage[idx] = keyOf(sims[i][j]);
        }
    __syncthreads();
    for (int s = 0; s < 64; s++) {
        int cnt = s_cnt[s];
        int b = s >> 1, neg = s & 1;
        unsigned int* dstBuf = (neg ? g_bufN0 : g_bufP) + (size_t)b * KQ + s_base[s];
        const unsigned int* srcP = stage + s_lofs[s];
        for (int i = t; i < cnt; i += MMTHREADS) dstBuf[i] = srcP[i];
    }
}

// ---------------- kernel 2: pos_min / neg_min ---------------------------------
__global__ void minmax_k(const int* __restrict__ topk) {
    int t = threadIdx.x;
    int cp = g_cntP[t], cn = g_cntN[t];
    #pragma unroll
    for (int off = 16; off; off >>= 1) {
        cp = min(cp, __shfl_down_sync(FULLMASK, cp, off));
        cn = min(cn, __shfl_down_sync(FULLMASK, cn, off));
    }
    if (t == 0) { g_pmm[0] = min(cp, topk[0]); g_pmm[1] = cn; }
}

// ---------------- top-10 of positives -----------------------------------------
__device__ __forceinline__ void insert10(unsigned int (&best)[10], unsigned int k) {
    if (k < best[9]) {
        int j = 9;
        #pragma unroll
        for (int s = 0; s < 9; s++) {
            if (j > 0 && best[j - 1] > k) { best[j] = best[j - 1]; j--; }
        }
        best[j] = k;
    }
}

__global__ void pos_part() {
    int c = blockIdx.x, row = blockIdx.y;
    int n = g_cntP[row];
    int per = (n + 15) >> 4;
    int s = c * per, e = min(s + per, n);
    const unsigned int* src = g_bufP + (size_t)row * KQ;
    int t = threadIdx.x;
    unsigned int bA[10], bB[10];
    #pragma unroll
    for (int i = 0; i < 10; i++) { bA[i] = 0xFFFFFFFFu; bB[i] = 0xFFFFFFFFu; }
    for (int base = s; base < e; base += 2048) {
        unsigned int k[8];
        #pragma unroll
        for (int qn = 0; qn < 8; qn++) {
            int idx = base + qn * 256 + t;
            k[qn] = (idx < e) ? src[idx] : 0xFFFFFFFFu;
        }
        insert10(bA, k[0]); insert10(bB, k[1]);
        insert10(bA, k[2]); insert10(bB, k[3]);
        insert10(bA, k[4]); insert10(bB, k[5]);
        insert10(bA, k[6]); insert10(bB, k[7]);
    }
    #pragma unroll
    for (int i = 0; i < 10; i++) {
        if (bB[i] >= bA[9]) break;
        insert10(bA, bB[i]);
    }
    __shared__ unsigned int sh[256 * 10];
    #pragma unroll
    for (int i = 0; i < 10; i++) sh[t * 10 + i] = bA[i];
    __syncthreads();
    for (int s2 = 128; s2 > 0; s2 >>= 1) {
        if (t < s2) {
            unsigned int* a  = &sh[t * 10];
            unsigned int* bl = &sh[(t + s2) * 10];
            unsigned int out[10]; int ia = 0, ib = 0;
            #pragma unroll
            for (int i = 0; i < 10; i++) {
                unsigned int va = (ia < 10) ? a[ia]  : 0xFFFFFFFFu;
                unsigned int vb = (ib < 10) ? bl[ib] : 0xFFFFFFFFu;
                if (va <= vb) { out[i] = va; ia++; } else { out[i] = vb; ib++; }
            }
            #pragma unroll
            for (int i = 0; i < 10; i++) a[i] = out[i];
        }
        __syncthreads();
    }
    if (t < 10) g_posPart[(row * 16 + c) * 10 + t] = sh[t];
}

__global__ void pos_merge() {
    int row = blockIdx.x;
    int lane = threadIdx.x;
    unsigned int v[5];
    #pragma unroll
    for (int j = 0; j < 5; j++) v[j] = g_posPart[row * 160 + lane * 5 + j];
    for (int i = 0; i < 10; i++) {
        unsigned int lmin = v[0];
        #pragma unroll
        for (int j = 1; j < 5; j++) lmin = min(lmin, v[j]);
        unsigned int wmin = lmin;
        #pragma unroll
        for (int off = 16; off; off >>= 1)
            wmin = min(wmin, __shfl_xor_sync(FULLMASK, wmin, off));
        unsigned int bal = __ballot_sync(FULLMASK, lmin == wmin);
        int leader = __ffs(bal) - 1;
        if (lane == leader) {
            bool done = false;
            #pragma unroll
            for (int j = 0; j < 5; j++) {
                if (!done && v[j] == wmin) { v[j] = 0xFFFFFFFFu; done = true; }
            }
        }
        if (lane == 0) g_posTop[row * 16 + i] = wmin;
    }
}

// ---------------- radix sort: 3x8-bit LSD over bits [8,32) --------------------
// bottom 8 bits left unsorted: elements equal in top 24 bits may be permuted,
// bounding per-element output error by 2^-15 relative (<< 1e-3 tolerance).
__global__ void rs_hist(int shift, int srcSel) {
    int chunk = blockIdx.x, row = blockIdx.y;
    int n = g_cntN[row];
    int s0 = chunk * 4096;
    __shared__ int h[256];
    int t = threadIdx.x;
    h[t] = 0;
    __syncthreads();
    if (s0 < n) {
        const unsigned int* in = (srcSel ? g_bufN1 : g_bufN0) + (size_t)row * KQ;
        int lim = min(4096, n - s0);
        for (int i = t; i < lim; i += 256)
            atomicAdd(&h[(in[s0 + i] >> shift) & 255], 1);
    }
    __syncthreads();
    g_histA[row * 8192 + t * 32 + chunk] = h[t];
}

__global__ void rs_scan() {
    int row = blockIdx.x;
    unsigned int* a = g_histA + row * 8192;
    int t = threadIdx.x;
    int v[32]; int sum = 0;
    int base = t * 32;
    #pragma unroll
    for (int i = 0; i < 32; i++) { v[i] = (int)a[base + i]; sum += v[i]; }
    __shared__ int ps[256];
    ps[t] = sum;
    __syncthreads();
    for (int off = 1; off < 256; off <<= 1) {
        int x = (t >= off) ? ps[t - off] : 0;
        __syncthreads();
        ps[t] += x;
        __syncthreads();
    }
    int run = (t > 0) ? ps[t - 1] : 0;
    #pragma unroll
    for (int i = 0; i < 32; i++) { int tmp = v[i]; a[base + i] = (unsigned)run; run += tmp; }
}

// warp-owned contiguous ranges; stable; sync-free ranking rounds.
__global__ __launch_bounds__(256)
void rs_scatter(int shift, int srcSel) {
    int chunk = blockIdx.x, row = blockIdx.y;
    int n = g_cntN[row];
    int s0 = chunk * 4096;
    if (s0 >= n) return;
    const unsigned int* in  = (srcSel ? g_bufN1 : g_bufN0) + (size_t)row * KQ;
    unsigned int*       out = (srcSel ? g_bufN0 : g_bufN1) + (size_t)row * KQ;
    const unsigned int* Hb  = g_histA + row * 8192;

    __shared__ unsigned int sKeys[4096];
    __shared__ int wh[8 * 256];     // per-warp hist -> running staged counters
    __shared__ int gb[256];
    __shared__ int lofs[256];
    __shared__ int ps[256];

    int t = threadIdx.x;
    int w = t >> 5, lane = t & 31;
    int wbase = s0 + 512 * w;       // warp-owned contiguous 512 keys

    // load keys: round j handles idx block [wbase+32j, wbase+32j+32)
    unsigned int myKeys[16];
    #pragma unroll
    for (int j = 0; j < 16; j++) {
        int idx = wbase + 32 * j + lane;
        myKeys[j] = (idx < n) ? in[idx] : 0xFFFFFFFFu;
    }

    #pragma unroll
    for (int qq = 0; qq < 8; qq++) wh[qq * 256 + t] = 0;
    __syncthreads();

    // Phase A: per-warp histograms
    #pragma unroll
    for (int j = 0; j < 16; j++) {
        int idx = wbase + 32 * j + lane;
        if (idx < n) atomicAdd(&wh[w * 256 + ((myKeys[j] >> shift) & 255)], 1);
    }
    __syncthreads();

    // Phase B: thread t owns digit t
    int tot = 0; int wstart[8];
    #pragma unroll
    for (int ww = 0; ww < 8; ww++) { wstart[ww] = tot; tot += wh[ww * 256 + t]; }
    ps[t] = tot;
    gb[t] = (int)Hb[t * 32 + chunk];
    __syncthreads();
    for (int off = 1; off < 256; off <<= 1) {
        int x = (t >= off) ? ps[t - off] : 0;
        __syncthreads();
        ps[t] += x;
        __syncthreads();
    }
    int lo = ps[t] - tot;
    lofs[t] = lo;
    #pragma unroll
    for (int ww = 0; ww < 8; ww++) wh[ww * 256 + t] = lo + wstart[ww];
    __syncthreads();

    // Phase C: sync-free stable staging
    #pragma unroll
    for (int j = 0; j < 16; j++) {
        int idx = wbase + 32 * j + lane;
        bool val = idx < n;
        unsigned int key = myKeys[j];
        int d = (key >> shift) & 255;
        unsigned int vm = __ballot_sync(FULLMASK, val);
        unsigned int peers = FULLMASK;
        #pragma unroll
        for (int bb = 0; bb < 8; ++bb) {
            unsigned int vote = __ballot_sync(FULLMASK, (d >> bb) & 1);
            peers &= ((d >> bb) & 1) ? vote : ~vote;
        }
        peers &= vm;
        int rank = __popc(peers & ((1u << lane) - 1u));
        int leader = peers ? (__ffs(peers) - 1) : 0;
        int basePos = 0;
        if (val && rank == 0) basePos = atomicAdd(&wh[w * 256 + d], __popc(peers));
        basePos = __shfl_sync(FULLMASK, basePos, leader);
        if (val) sKeys[basePos + rank] = key;
    }
    __syncthreads();

    // coalesced copy-out in digit runs
    int lim = min(4096, n - s0);
    for (int pos = t; pos < lim; pos += 256) {
        unsigned int key = sKeys[pos];
        int d = (key >> shift) & 255;
        out[gb[d] + (pos - lofs[d])] = key;
    }
}

// ---------------- writer (final sorted negatives live in g_bufN1) -------------
__global__ void write_k(float* __restrict__ out) {
    int r = blockIdx.y;
    unsigned int pm = (unsigned int)g_pmm[0];
    unsigned int nm = (unsigned int)g_pmm[1];
    if ((unsigned)r >= 32u * pm) return;
    unsigned int width = nm + 1u;
    unsigned int b = (unsigned)r / pm;
    unsigned int p = (unsigned)r - b * pm;
    const float invT = 1.0f / 0.07f;
    size_t rowBase = (size_t)r * width;
    const unsigned int* negRow = g_bufN1 + (size_t)b * KQ;

    unsigned int qlen = (width + 3u) >> 2;
    unsigned int c = blockIdx.x * qlen + threadIdx.x;
    unsigned int cend = min((blockIdx.x + 1u) * qlen, width);
    if (c >= cend) return;
    if (c == 0u) {
        out[rowBase] = valOf(g_posTop[b * 16 + p]) * invT;
        c += 256u;
        if (c >= cend) return;
    }
    unsigned int num = p * nm + (c - 1u);
    unsigned int qi = num / pm;
    unsigned int rem = num - qi * pm;
    unsigned int d256 = 256u / pm;
    unsigned int r256 = 256u - d256 * pm;
    while (c < cend) {
        out[rowBase + c] = valOf(negRow[qi]) * invT;
        c += 256u;
        qi += d256;
        rem += r256;
        if (rem >= pm) { rem -= pm; qi += 1u; }
    }
}

// ---------------- launcher ----------------------------------------------------
extern "C" void kernel_launch(void* const* d_in, const int* in_sizes, int n_in,
                              void* d_out, int out_size) {
    const float* q     = (const float*)d_in[0];
    const float* fq    = (const float*)d_in[1];
    const int* lab_q   = (const int*)d_in[2];
    const int* clu_q   = (const int*)d_in[3];
    const int* lab_k   = (const int*)d_in[4];
    const int* clu_k   = (const int*)d_in[5];
    const int* topk    = (const int*)d_in[6];
    float* out = (float*)d_out;

    cudaFuncSetAttribute(mm_part, cudaFuncAttributeMaxDynamicSharedMemorySize, (int)SMEM_MM);

    zero_k<<<1, 32>>>();
    mm_part<<<KQ / KT, MMTHREADS, SMEM_MM>>>(q, fq, lab_q, clu_q, lab_k, clu_k);
    minmax_k<<<1, 32>>>(topk);
    pos_part<<<dim3(16, B), 256>>>();
    pos_merge<<<B, 32>>>();
    for (int pass = 0; pass < 3; ++pass) {
        int shift = 8 + pass * 8;        // sort bits [8,32)
        rs_hist<<<dim3(32, B), 256>>>(shift, pass & 1);
        rs_scan<<<B, 256>>>();
        rs_scatter<<<dim3(32, B), 256>>>(shift, pass & 1);
    }
    write_k<<<dim3(4, 320), 256>>>(out);
}